// round 7
// baseline (speedup 1.0000x reference)
#include <cuda_runtime.h>

#define NPL   50000
#define L_TOT 6
#define KN    8
#define FEAT  32
#define H     128
#define MT    48      // nodes per block
#define NT    256     // two 128-thread feature groups
#define NPT   24      // nodes per thread (per group)
#define EMT   32      // embed: nodes per block
#define FROW  36

__device__ __forceinline__ float htanh(float x) {
    float y; asm("tanh.approx.f32 %0, %1;" : "=f"(y) : "f"(x)); return y;
}

// One dense stage: sO[m][f] = tanh(b[f] + sX[m].W (+ sY[m].W2))
// thread owns feature f, processes NPT nodes starting at m0. All smem rows stride H.
template<bool CAT>
__device__ __forceinline__ void stage(const float* __restrict__ sX,
                                      const float* __restrict__ sY,
                                      const float* __restrict__ W,
                                      const float* __restrict__ b,
                                      float* __restrict__ sO, int f, int m0)
{
    float acc[NPT];
    float bias = __ldg(b + f);
#pragma unroll
    for (int m = 0; m < NPT; m++) acc[m] = bias;

#pragma unroll 2
    for (int k = 0; k < H; k += 4) {
        float w0 = __ldg(W + (k+0)*H + f);
        float w1 = __ldg(W + (k+1)*H + f);
        float w2 = __ldg(W + (k+2)*H + f);
        float w3 = __ldg(W + (k+3)*H + f);
#pragma unroll
        for (int m = 0; m < NPT; m++) {
            float4 a = *reinterpret_cast<const float4*>(sX + (m0 + m)*H + k);
            acc[m] = fmaf(a.x, w0, acc[m]);
            acc[m] = fmaf(a.y, w1, acc[m]);
            acc[m] = fmaf(a.z, w2, acc[m]);
            acc[m] = fmaf(a.w, w3, acc[m]);
        }
    }
    if (CAT) {
        const float* __restrict__ W2 = W + H * H;
#pragma unroll 2
        for (int k = 0; k < H; k += 4) {
            float w0 = __ldg(W2 + (k+0)*H + f);
            float w1 = __ldg(W2 + (k+1)*H + f);
            float w2 = __ldg(W2 + (k+2)*H + f);
            float w3 = __ldg(W2 + (k+3)*H + f);
#pragma unroll
            for (int m = 0; m < NPT; m++) {
                float4 a = *reinterpret_cast<const float4*>(sY + (m0 + m)*H + k);
                acc[m] = fmaf(a.x, w0, acc[m]);
                acc[m] = fmaf(a.y, w1, acc[m]);
                acc[m] = fmaf(a.z, w2, acc[m]);
                acc[m] = fmaf(a.w, w3, acc[m]);
            }
        }
    }
#pragma unroll
    for (int m = 0; m < NPT; m++) sO[(m0 + m)*H + f] = htanh(acc[m]);
}

// base = tanh(nf @ W_embed + b_embed) -> emb (= d_out)
__global__ void __launch_bounds__(128)
embed_kernel(const float* __restrict__ nf, const float* __restrict__ W,
             const float* __restrict__ b, float* __restrict__ out, int n_nodes)
{
    __shared__ float S[EMT * FROW];
    int t    = threadIdx.x;
    int f    = t;
    int base = blockIdx.x * EMT;

    for (int i = t; i < EMT * FEAT; i += 128) {
        int m = i / FEAT, k = i % FEAT;
        int row = base + m;
        if (row >= n_nodes) row = n_nodes - 1;
        S[m * FROW + k] = nf[(long)row * FEAT + k];
    }
    __syncthreads();

    float acc[EMT];
    float bias = __ldg(b + f);
#pragma unroll
    for (int m = 0; m < EMT; m++) acc[m] = bias;

#pragma unroll 2
    for (int k = 0; k < FEAT; k += 4) {
        float w0 = __ldg(W + (k+0)*H + f);
        float w1 = __ldg(W + (k+1)*H + f);
        float w2 = __ldg(W + (k+2)*H + f);
        float w3 = __ldg(W + (k+3)*H + f);
#pragma unroll
        for (int m = 0; m < EMT; m++) {
            float4 a = *reinterpret_cast<const float4*>(S + m*FROW + k);
            acc[m] = fmaf(a.x, w0, acc[m]);
            acc[m] = fmaf(a.y, w1, acc[m]);
            acc[m] = fmaf(a.z, w2, acc[m]);
            acc[m] = fmaf(a.w, w3, acc[m]);
        }
    }
#pragma unroll
    for (int m = 0; m < EMT; m++) {
        int row = base + m;
        if (row < n_nodes) out[(long)row * H + f] = htanh(acc[m]);
    }
}

// Full GNN layer l: gather(K=8) -> 11 dense-tanh stages -> write emb block l.
// 256 threads: group g = tid/128 handles nodes [g*NPT, g*NPT+NPT), f = tid%128.
__global__ void __launch_bounds__(NT, 2)
layer_kernel(float* emb,
             const int* __restrict__ src, int l,
             const float* __restrict__ Wmp0, const float* __restrict__ bmp0,
             const float* __restrict__ Wmp1, const float* __restrict__ bmp1,
             const float* __restrict__ Wmpc, const float* __restrict__ bmpc,
             const float* __restrict__ Wne0, const float* __restrict__ bne0,
             const float* __restrict__ Wne1, const float* __restrict__ bne1,
             const float* __restrict__ Wnec, const float* __restrict__ bnec)
{
    extern __shared__ float smem[];
    float* A = smem;                 // [MT][H]
    float* B = A + MT * H;
    float* C = B + MT * H;
    int*   sidx = (int*)(C + MT * H);  // [MT][KN]

    int t  = threadIdx.x;
    int f  = t & 127;
    int g  = t >> 7;
    int m0 = g * NPT;
    int d0 = blockIdx.x * MT;

    const int* __restrict__ srcL = src + (long)(l - 1) * NPL * KN;
    for (int i = t; i < MT * KN; i += NT) {
        int node = d0 + i / KN;
        if (node >= NPL) node = NPL - 1;
        sidx[i] = srcL[(long)node * KN + (i % KN)];
    }
    __syncthreads();

    // gather: A[m][f] = sum over 8 neighbors (coalesced LDG across f, L2-hot)
#pragma unroll 2
    for (int m = 0; m < NPT; m++) {
        float s = 0.f;
#pragma unroll
        for (int k = 0; k < KN; k++) {
            int row = sidx[(m0 + m) * KN + k];
            s += __ldg(emb + (long)row * H + f);
        }
        A[(m0 + m) * H + f] = s;
    }
    __syncthreads();

    // message-passing MLP
    stage<false>(A, nullptr, Wmp0, bmp0, B, f, m0); __syncthreads();      // r0 -> B
    stage<false>(B, nullptr, Wmp1, bmp1, C, f, m0); __syncthreads();      // r  -> C
    stage<true >(C, B, Wmpc + 0*2*H*H, bmpc + 0*H, A, f, m0); __syncthreads();
    stage<true >(A, B, Wmpc + 1*2*H*H, bmpc + 1*H, C, f, m0); __syncthreads();
    stage<true >(C, B, Wmpc + 2*2*H*H, bmpc + 2*H, A, f, m0); __syncthreads();
    stage<true >(A, B, Wmpc + 3*2*H*H, bmpc + 3*H, C, f, m0); __syncthreads(); // r -> C

    // this layer's base embedding -> A
#pragma unroll 2
    for (int m = 0; m < NPT; m++) {
        int node = d0 + m0 + m;
        if (node >= NPL) node = NPL - 1;
        A[(m0 + m) * H + f] = __ldg(emb + (long)(l * NPL + node) * H + f);
    }
    __syncthreads();

    // node-embedding MLP
    stage<true >(A, C, Wne0, bne0, B, f, m0); __syncthreads();            // c0 -> B
    stage<false>(B, nullptr, Wne1, bne1, A, f, m0); __syncthreads();      // e  -> A
    stage<true >(A, B, Wnec + 0*2*H*H, bnec + 0*H, C, f, m0); __syncthreads();
    stage<true >(C, B, Wnec + 1*2*H*H, bnec + 1*H, A, f, m0); __syncthreads();
    stage<true >(A, B, Wnec + 2*2*H*H, bnec + 2*H, C, f, m0); __syncthreads();
    stage<true >(C, B, Wnec + 3*2*H*H, bnec + 3*H, A, f, m0); __syncthreads(); // e -> A

#pragma unroll 2
    for (int m = 0; m < NPT; m++) {
        int node = d0 + m0 + m;
        if (node < NPL)
            emb[(long)(l * NPL + node) * H + f] = A[(m0 + m) * H + f];
    }
}

extern "C" void kernel_launch(void* const* d_in, const int* in_sizes, int n_in,
                              void* d_out, int out_size)
{
    const float* nf      = (const float*)d_in[0];
    const int*   src     = (const int*)  d_in[1];
    const float* W_embed = (const float*)d_in[3];
    const float* b_embed = (const float*)d_in[4];
    const float* W_mp0   = (const float*)d_in[5];
    const float* b_mp0   = (const float*)d_in[6];
    const float* W_mp1   = (const float*)d_in[7];
    const float* b_mp1   = (const float*)d_in[8];
    const float* W_mpc   = (const float*)d_in[9];
    const float* b_mpc   = (const float*)d_in[10];
    const float* W_ne0   = (const float*)d_in[11];
    const float* b_ne0   = (const float*)d_in[12];
    const float* W_ne1   = (const float*)d_in[13];
    const float* b_ne1   = (const float*)d_in[14];
    const float* W_nec   = (const float*)d_in[15];
    const float* b_nec   = (const float*)d_in[16];

    float* out = (float*)d_out;

    const int smem_bytes = (3 * MT * H) * sizeof(float) + MT * KN * sizeof(int);
    cudaFuncSetAttribute(layer_kernel, cudaFuncAttributeMaxDynamicSharedMemorySize, smem_bytes);

    const int n_nodes = L_TOT * NPL;
    embed_kernel<<<(n_nodes + EMT - 1) / EMT, 128>>>(nf, W_embed, b_embed, out, n_nodes);

    const int layer_blocks = (NPL + MT - 1) / MT;
    for (int l = 1; l < L_TOT; l++) {
        layer_kernel<<<layer_blocks, NT, smem_bytes>>>(out, src, l,
                                           W_mp0, b_mp0, W_mp1, b_mp1, W_mpc, b_mpc,
                                           W_ne0, b_ne0, W_ne1, b_ne1, W_nec, b_nec);
    }
}